// round 1
// baseline (speedup 1.0000x reference)
#include <cuda_runtime.h>

#define BETA   0.95f
#define THRESH 1.0f

constexpr int NI = 80, NH = 256, NC = 2, T = 200, BATCH = 4096;
constexpr int NB   = 32;           // batch rows per block
constexpr int NBLK = BATCH / NB;   // 128 blocks
constexpr int NTHR = 256;

// Transposed weights (i-major) so GEMM weight loads are coalesced LDG.128.
__device__ float g_W1T[NI * NH];
__device__ float g_W2T[NH * NH];
__device__ float g_W3T[NH * NH];

__global__ void prep_transpose(const float* __restrict__ W1,
                               const float* __restrict__ W2,
                               const float* __restrict__ W3) {
    int idx = blockIdx.x * 256 + threadIdx.x;   // grid 256x256 covers 65536
    if (idx < NI * NH) {
        int i = idx >> 8, j = idx & 255;
        g_W1T[idx] = W1[j * NI + i];
    }
    if (idx < NH * NH) {
        int i = idx >> 8, j = idx & 255;
        g_W2T[idx] = W2[j * NH + i];
        g_W3T[idx] = W3[j * NH + i];
    }
}

// snntorch Leaky, reset_mechanism='subtract':
//   reset from PREVIOUS mem, spike from UPDATED mem.
__device__ __forceinline__ float lif_update(float mo, float cur, float& spk) {
    float mn = BETA * mo + cur - ((mo > THRESH) ? THRESH : 0.0f);
    spk = (mn > THRESH) ? 1.0f : 0.0f;
    return mn;
}

// One layer: cur[b,j] = bias[j] + sum_i sA[b,i] * WT[i,j]; then LIF update of
// m[b,j] and spike write to s_out[b,j]. Thread tile: 4 batch x 8 hidden.
// sA may alias s_out (sync separates read phase from write phase).
template<int K>
__device__ __forceinline__ void layer_gemm_lif(
    const float* __restrict__ WT, const float* __restrict__ sA,
    const float* __restrict__ sbias, float* __restrict__ m,
    float* __restrict__ s_out, int lane, int wid)
{
    const int jx  = lane * 4;   // j in {jx..jx+3} and {128+jx..128+jx+3}
    const int bb0 = wid * 4;    // 4 batch rows per warp-group

    float acc[4][8];
    const float4 bA = *(const float4*)(sbias + jx);
    const float4 bB = *(const float4*)(sbias + 128 + jx);
#pragma unroll
    for (int bb = 0; bb < 4; bb++) {
        acc[bb][0] = bA.x; acc[bb][1] = bA.y; acc[bb][2] = bA.z; acc[bb][3] = bA.w;
        acc[bb][4] = bB.x; acc[bb][5] = bB.y; acc[bb][6] = bB.z; acc[bb][7] = bB.w;
    }

#pragma unroll 2
    for (int ic = 0; ic < K; ic += 4) {
        float4 sv0 = *(const float4*)(sA + (bb0 + 0) * K + ic);
        float4 sv1 = *(const float4*)(sA + (bb0 + 1) * K + ic);
        float4 sv2 = *(const float4*)(sA + (bb0 + 2) * K + ic);
        float4 sv3 = *(const float4*)(sA + (bb0 + 3) * K + ic);
        const float* sv[4] = { (const float*)&sv0, (const float*)&sv1,
                               (const float*)&sv2, (const float*)&sv3 };
#pragma unroll
        for (int ii = 0; ii < 4; ii++) {
            const float4 wA = *(const float4*)(WT + (ic + ii) * NH + jx);
            const float4 wB = *(const float4*)(WT + (ic + ii) * NH + 128 + jx);
#pragma unroll
            for (int bb = 0; bb < 4; bb++) {
                const float s = sv[bb][ii];
                acc[bb][0] = fmaf(wA.x, s, acc[bb][0]);
                acc[bb][1] = fmaf(wA.y, s, acc[bb][1]);
                acc[bb][2] = fmaf(wA.z, s, acc[bb][2]);
                acc[bb][3] = fmaf(wA.w, s, acc[bb][3]);
                acc[bb][4] = fmaf(wB.x, s, acc[bb][4]);
                acc[bb][5] = fmaf(wB.y, s, acc[bb][5]);
                acc[bb][6] = fmaf(wB.z, s, acc[bb][6]);
                acc[bb][7] = fmaf(wB.w, s, acc[bb][7]);
            }
        }
    }
    __syncthreads();   // all reads of sA complete before spikes overwrite it

#pragma unroll
    for (int bb = 0; bb < 4; bb++) {
        const int b = bb0 + bb;
        float* mrow = m + b * NH;
        float* srow = s_out + b * NH;
#pragma unroll
        for (int g = 0; g < 2; g++) {
            const int j = g * 128 + jx;
            float4 mv = *(float4*)(mrow + j);
            float4 sp;
            mv.x = lif_update(mv.x, acc[bb][g * 4 + 0], sp.x);
            mv.y = lif_update(mv.y, acc[bb][g * 4 + 1], sp.y);
            mv.z = lif_update(mv.z, acc[bb][g * 4 + 2], sp.z);
            mv.w = lif_update(mv.w, acc[bb][g * 4 + 3], sp.w);
            *(float4*)(mrow + j) = mv;
            *(float4*)(srow + j) = sp;
        }
    }
    __syncthreads();   // spikes visible to all before next layer reads them
}

__global__ void __launch_bounds__(NTHR, 1) snn_kernel(
    const float* __restrict__ x,
    const float* __restrict__ b1, const float* __restrict__ b2,
    const float* __restrict__ b3, const float* __restrict__ W4,
    const float* __restrict__ b4, float* __restrict__ out)
{
    extern __shared__ float sm[];
    float* s_x   = sm;                  // NB*NI   = 2560
    float* s_spk = s_x + NB * NI;       // NB*NH   = 8192 (s1/s2/s3 reuse)
    float* m1    = s_spk + NB * NH;     // NB*NH
    float* m2    = m1 + NB * NH;        // NB*NH
    float* m3    = m2 + NB * NH;        // NB*NH
    float* sb1   = m3 + NB * NH;        // NH
    float* sb2   = sb1 + NH;            // NH
    float* sb3   = sb2 + NH;            // NH
    float* sW4   = sb3 + NH;            // NC*NH
    float* sb4   = sW4 + NC * NH;       // NC
    float* m4    = sb4 + NC;            // NB*NC

    const int tid  = threadIdx.x;
    const int lane = tid & 31;
    const int wid  = tid >> 5;
    const int b0   = blockIdx.x * NB;

    for (int k = tid; k < NB * NH; k += NTHR) { m1[k] = 0.f; m2[k] = 0.f; m3[k] = 0.f; }
    if (tid < NH) { sb1[tid] = b1[tid]; sb2[tid] = b2[tid]; sb3[tid] = b3[tid]; }
    for (int k = tid; k < NC * NH; k += NTHR) sW4[k] = W4[k];
    if (tid < NC) sb4[tid] = b4[tid];
    if (tid < NB * NC) m4[tid] = 0.f;
    __syncthreads();

    for (int t = 0; t < T; ++t) {
        // Stage x[:, :, t] for this block's batch rows. Stride-200 reads hit
        // 32B sectors that stay cached across consecutive t.
        for (int k = tid; k < NB * NI; k += NTHR) {
            int b = k / NI, i = k - b * NI;
            s_x[k] = x[((size_t)(b0 + b) * NI + i) * T + t];
        }
        __syncthreads();

        layer_gemm_lif<NI>(g_W1T, s_x,   sb1, m1, s_spk, lane, wid);
        layer_gemm_lif<NH>(g_W2T, s_spk, sb2, m2, s_spk, lane, wid);
        layer_gemm_lif<NH>(g_W3T, s_spk, sb3, m3, s_spk, lane, wid);

        // Layer 4: 2 classes. 64 threads: thread = (b, c). Rotated shared
        // reads (b*8) avoid N-way bank conflicts across b.
        if (tid < NB * NC) {
            const int b = tid >> 1, c = tid & 1;
            const float* sr = s_spk + b * NH;
            const float* wr = sW4 + c * NH;
            float a0 = sb4[c], a1 = 0.f, a2 = 0.f, a3 = 0.f;
#pragma unroll 4
            for (int i = 0; i < NH; i += 16) {
                int i0 = (i + b * 8) & (NH - 1);
                int i1 = (i + 4 + b * 8) & (NH - 1);
                int i2 = (i + 8 + b * 8) & (NH - 1);
                int i3 = (i + 12 + b * 8) & (NH - 1);
                float4 s0 = *(const float4*)(sr + i0); float4 w0 = *(const float4*)(wr + i0);
                float4 s1 = *(const float4*)(sr + i1); float4 w1 = *(const float4*)(wr + i1);
                float4 s2 = *(const float4*)(sr + i2); float4 w2 = *(const float4*)(wr + i2);
                float4 s3 = *(const float4*)(sr + i3); float4 w3 = *(const float4*)(wr + i3);
                a0 = fmaf(s0.x, w0.x, a0); a0 = fmaf(s0.y, w0.y, a0);
                a0 = fmaf(s0.z, w0.z, a0); a0 = fmaf(s0.w, w0.w, a0);
                a1 = fmaf(s1.x, w1.x, a1); a1 = fmaf(s1.y, w1.y, a1);
                a1 = fmaf(s1.z, w1.z, a1); a1 = fmaf(s1.w, w1.w, a1);
                a2 = fmaf(s2.x, w2.x, a2); a2 = fmaf(s2.y, w2.y, a2);
                a2 = fmaf(s2.z, w2.z, a2); a2 = fmaf(s2.w, w2.w, a2);
                a3 = fmaf(s3.x, w3.x, a3); a3 = fmaf(s3.y, w3.y, a3);
                a3 = fmaf(s3.z, w3.z, a3); a3 = fmaf(s3.w, w3.w, a3);
            }
            float cur = (a0 + a1) + (a2 + a3);
            float spk;
            m4[tid] = lif_update(m4[tid], cur, spk);
            // out[t, b0+b, c] — 64 consecutive floats per block: coalesced.
            out[(size_t)t * (BATCH * NC) + b0 * NC + tid] = spk;
        }
        // No extra sync needed: next iteration's x-stage __syncthreads()
        // orders layer-4 spike reads before layer-1 overwrites s_spk.
    }
}

extern "C" void kernel_launch(void* const* d_in, const int* in_sizes, int n_in,
                              void* d_out, int out_size) {
    const float* x  = (const float*)d_in[0];
    const float* W1 = (const float*)d_in[1];
    const float* b1 = (const float*)d_in[2];
    const float* W2 = (const float*)d_in[3];
    const float* b2 = (const float*)d_in[4];
    const float* W3 = (const float*)d_in[5];
    const float* b3 = (const float*)d_in[6];
    const float* W4 = (const float*)d_in[7];
    const float* b4 = (const float*)d_in[8];
    float* out = (float*)d_out;

    prep_transpose<<<256, 256>>>(W1, W2, W3);

    const int smem_bytes =
        (NB * NI + 4 * NB * NH + 3 * NH + NC * NH + NC + NB * NC) * (int)sizeof(float);
    cudaFuncSetAttribute(snn_kernel,
                         cudaFuncAttributeMaxDynamicSharedMemorySize, smem_bytes);
    snn_kernel<<<NBLK, NTHR, smem_bytes>>>(x, b1, b2, b3, W4, b4, out);
}